// round 1
// baseline (speedup 1.0000x reference)
#include <cuda_runtime.h>

#define CB 4
#define CT 2048
#define CD 1024
#define CH 16
#define CDK 64
#define NTOK 8192      // CB*CT
#define NBH  64        // CB*CH
#define ASCALE 0.125f

// ---------------- scratch (static device allocations) ----------------
__device__ float g_xn[NTOK * CD];
__device__ float g_Q[NTOK * CD];     // [bh][t][dk]
__device__ float g_Kt[NTOK * CD];    // [bh][dk][t]  (pre-transposed for attention)
__device__ float g_V[NTOK * CD];     // [bh][t][dk]
__device__ float g_AO[NTOK * CD];    // attention output, [b*T + t][D]
__device__ float g_maskf[NTOK];

// ---------------- mask decode (dtype-robust) ----------------
__global__ void decode_mask_kernel(const unsigned char* __restrict__ raw) {
    __shared__ int s_big, s_nzoff, s_nz4, s_nz23;
    if (threadIdx.x == 0) { s_big = 0; s_nzoff = 0; s_nz4 = 0; s_nz23 = 0; }
    __syncthreads();
    int big = 0, nzoff = 0, nz4 = 0, nz23 = 0;
    for (int i = threadIdx.x; i < NTOK; i += blockDim.x) {
        unsigned char v = raw[i];
        if (v > 1) big = 1;
        if (v != 0) {
            if ((i & 3) != 0) nzoff = 1;
            int m8 = i & 7;
            if (m8 >= 4) nz4 = 1;
            if (m8 == 2 || m8 == 3) nz23 = 1;
        }
    }
    if (big)   atomicOr(&s_big, 1);
    if (nzoff) atomicOr(&s_nzoff, 1);
    if (nz4)   atomicOr(&s_nz4, 1);
    if (nz23)  atomicOr(&s_nz23, 1);
    __syncthreads();
    // 0=u8/bool, 1=i32, 2=f32, 3=i64, 4=f64
    int cls;
    if (s_big)        cls = s_nz23 ? 2 : 4;
    else if (s_nzoff) cls = 0;
    else              cls = s_nz4 ? 1 : 3;
    for (int i = threadIdx.x; i < NTOK; i += blockDim.x) {
        float m;
        if (cls == 0)      m = raw[i] ? 1.0f : 0.0f;
        else if (cls == 1) m = (((const int*)raw)[i] != 0) ? 1.0f : 0.0f;
        else if (cls == 2) m = (((const float*)raw)[i] != 0.0f) ? 1.0f : 0.0f;
        else if (cls == 3) m = (((const long long*)raw)[i] != 0) ? 1.0f : 0.0f;
        else               m = (((const double*)raw)[i] != 0.0) ? 1.0f : 0.0f;
        g_maskf[i] = m;
    }
}

// ---------------- layernorm ----------------
__global__ void layernorm_kernel(const float* __restrict__ x,
                                 const float* __restrict__ gam,
                                 const float* __restrict__ bet) {
    int row = blockIdx.x;
    int t = threadIdx.x;   // 256 threads, each handles one float4 (1024 floats)
    const float4* xr = reinterpret_cast<const float4*>(x + (size_t)row * CD);
    float4 v = xr[t];
    float s = v.x + v.y + v.z + v.w;
    float q = v.x * v.x + v.y * v.y + v.z * v.z + v.w * v.w;
    __shared__ float red[20];
#pragma unroll
    for (int m = 16; m > 0; m >>= 1) {
        s += __shfl_xor_sync(0xffffffffu, s, m);
        q += __shfl_xor_sync(0xffffffffu, q, m);
    }
    int w = t >> 5, lane = t & 31;
    if (lane == 0) { red[w] = s; red[8 + w] = q; }
    __syncthreads();
    if (t == 0) {
        float S = 0.f, Qq = 0.f;
#pragma unroll
        for (int i = 0; i < 8; i++) { S += red[i]; Qq += red[8 + i]; }
        float mu = S * (1.0f / CD);
        float var = Qq * (1.0f / CD) - mu * mu;
        red[16] = mu;
        red[17] = rsqrtf(var + 1e-5f);
    }
    __syncthreads();
    float mu = red[16], inv = red[17];
    float4 g4 = reinterpret_cast<const float4*>(gam)[t];
    float4 b4 = reinterpret_cast<const float4*>(bet)[t];
    float4 o;
    o.x = (v.x - mu) * inv * g4.x + b4.x;
    o.y = (v.y - mu) * inv * g4.y + b4.y;
    o.z = (v.z - mu) * inv * g4.z + b4.z;
    o.w = (v.w - mu) * inv * g4.w + b4.w;
    reinterpret_cast<float4*>(g_xn + (size_t)row * CD)[t] = o;
}

// ---------------- GEMM core: C[128x128] = A[128xK] * W[128xK]^T ----------------
#define GBM 128
#define GBN 128
#define GBK 8
#define GST 132

__device__ __forceinline__ void gemm_core(const float* __restrict__ A,
                                          const float* __restrict__ W,
                                          int cM, int cN,
                                          float acc[8][8],
                                          float* As, float* Bs) {
    int t = threadIdx.x;
    int lrow = t >> 1, lc4 = (t & 1) * 4;
    const float* Ap = A + (size_t)(cM * GBM + lrow) * CD + lc4;
    const float* Wp = W + (size_t)(cN * GBN + lrow) * CD + lc4;
    int tm = t >> 4, tn = t & 15;
    for (int kt = 0; kt < CD; kt += GBK) {
        float4 av = *reinterpret_cast<const float4*>(Ap + kt);
        float4 wv = *reinterpret_cast<const float4*>(Wp + kt);
        __syncthreads();
        As[(lc4 + 0) * GST + lrow] = av.x;
        As[(lc4 + 1) * GST + lrow] = av.y;
        As[(lc4 + 2) * GST + lrow] = av.z;
        As[(lc4 + 3) * GST + lrow] = av.w;
        Bs[(lc4 + 0) * GST + lrow] = wv.x;
        Bs[(lc4 + 1) * GST + lrow] = wv.y;
        Bs[(lc4 + 2) * GST + lrow] = wv.z;
        Bs[(lc4 + 3) * GST + lrow] = wv.w;
        __syncthreads();
#pragma unroll
        for (int k = 0; k < GBK; k++) {
            float ra[8], rb[8];
            *reinterpret_cast<float4*>(ra)     = *reinterpret_cast<float4*>(As + k * GST + tm * 8);
            *reinterpret_cast<float4*>(ra + 4) = *reinterpret_cast<float4*>(As + k * GST + tm * 8 + 4);
            *reinterpret_cast<float4*>(rb)     = *reinterpret_cast<float4*>(Bs + k * GST + tn * 8);
            *reinterpret_cast<float4*>(rb + 4) = *reinterpret_cast<float4*>(Bs + k * GST + tn * 8 + 4);
#pragma unroll
            for (int i = 0; i < 8; i++)
#pragma unroll
                for (int j = 0; j < 8; j++)
                    acc[i][j] += ra[i] * rb[j];
        }
    }
}

// ---------------- QKV projection ----------------
__global__ __launch_bounds__(256, 2) void gemm_qkv_kernel(
    const float* __restrict__ wq, const float* __restrict__ wk, const float* __restrict__ wv,
    const float* __restrict__ bq, const float* __restrict__ bk, const float* __restrict__ bv) {
    __shared__ float As[GBK * GST], Bs[GBK * GST];
    int z = blockIdx.z;
    const float* W    = (z == 0) ? wq : (z == 1) ? wk : wv;
    const float* bias = (z == 0) ? bq : (z == 1) ? bk : bv;
    float acc[8][8];
#pragma unroll
    for (int i = 0; i < 8; i++)
#pragma unroll
        for (int j = 0; j < 8; j++) acc[i][j] = 0.f;
    gemm_core(g_xn, W, blockIdx.y, blockIdx.x, acc, As, Bs);

    int t = threadIdx.x, tm = t >> 4, tn = t & 15;
    int n0 = blockIdx.y * GBM + tm * 8;
    int e0 = blockIdx.x * GBN + tn * 8;
    float bv8[8];
#pragma unroll
    for (int j = 0; j < 8; j++) bv8[j] = bias[e0 + j];
#pragma unroll
    for (int i = 0; i < 8; i++) {
        int n = n0 + i;
        int bb = n >> 11;          // n / T
        int tok = n & 2047;        // n % T
#pragma unroll
        for (int j = 0; j < 8; j++) {
            int e = e0 + j;
            int h = e >> 6, dk = e & 63;
            int bh = bb * CH + h;
            float val = acc[i][j] + bv8[j];
            if (z == 0)      g_Q [((size_t)bh * CT + tok) * CDK + dk] = val;
            else if (z == 1) g_Kt[((size_t)bh * CDK + dk) * CT + tok] = val;
            else             g_V [((size_t)bh * CT + tok) * CDK + dk] = val;
        }
    }
}

// ---------------- output projection (*0.5) ----------------
__global__ __launch_bounds__(256, 2) void gemm_oproj_kernel(
    const float* __restrict__ wo, const float* __restrict__ bo, float* __restrict__ out) {
    __shared__ float As[GBK * GST], Bs[GBK * GST];
    float acc[8][8];
#pragma unroll
    for (int i = 0; i < 8; i++)
#pragma unroll
        for (int j = 0; j < 8; j++) acc[i][j] = 0.f;
    gemm_core(g_AO, wo, blockIdx.y, blockIdx.x, acc, As, Bs);

    int t = threadIdx.x, tm = t >> 4, tn = t & 15;
    int n0 = blockIdx.y * GBM + tm * 8;
    int e0 = blockIdx.x * GBN + tn * 8;
    float bv8[8];
#pragma unroll
    for (int j = 0; j < 8; j++) bv8[j] = bo[e0 + j];
#pragma unroll
    for (int i = 0; i < 8; i++) {
        int n = n0 + i;
        float4 o1, o2;
        o1.x = (acc[i][0] + bv8[0]) * 0.5f;
        o1.y = (acc[i][1] + bv8[1]) * 0.5f;
        o1.z = (acc[i][2] + bv8[2]) * 0.5f;
        o1.w = (acc[i][3] + bv8[3]) * 0.5f;
        o2.x = (acc[i][4] + bv8[4]) * 0.5f;
        o2.y = (acc[i][5] + bv8[5]) * 0.5f;
        o2.z = (acc[i][6] + bv8[6]) * 0.5f;
        o2.w = (acc[i][7] + bv8[7]) * 0.5f;
        *reinterpret_cast<float4*>(out + (size_t)n * CD + e0)     = o1;
        *reinterpret_cast<float4*>(out + (size_t)n * CD + e0 + 4) = o2;
    }
}

// ---------------- L2 norm of Q rows (in place) ----------------
__global__ void l2norm_q_kernel() {
    int gid = blockIdx.x * blockDim.x + threadIdx.x;
    int w = gid >> 5, lane = gid & 31;     // w in [0, 131072)
    float2* p = reinterpret_cast<float2*>(g_Q + (size_t)w * CDK) + lane;
    float2 v = *p;
    float s = v.x * v.x + v.y * v.y;
#pragma unroll
    for (int m = 16; m > 0; m >>= 1) s += __shfl_xor_sync(0xffffffffu, s, m);
    float inv = 1.0f / fmaxf(sqrtf(s), 1e-8f);
    v.x *= inv; v.y *= inv;
    *p = v;
}

// ---------------- L2 norm of K (transposed layout, column-wise) ----------------
__global__ void l2norm_kt_kernel() {
    int bh = blockIdx.y;
    int tok = blockIdx.x * 256 + threadIdx.x;
    float* base = g_Kt + (size_t)bh * CDK * CT + tok;
    float v[CDK];
    float s = 0.f;
#pragma unroll
    for (int d = 0; d < CDK; d++) { v[d] = base[(size_t)d * CT]; s += v[d] * v[d]; }
    float inv = 1.0f / fmaxf(sqrtf(s), 1e-8f);
#pragma unroll
    for (int d = 0; d < CDK; d++) base[(size_t)d * CT] = v[d] * inv;
}

// ---------------- attention ----------------
#define SA2 68   // smem row stride (floats): 16B-aligned, bank-rotating

__global__ __launch_bounds__(256) void attn_kernel() {
    extern __shared__ float sm[];
    float* Qs  = sm;                 // [64][SA2]   Q[q][d]
    float* Kts = sm + 64 * SA2;      // [64][SA2]   K^T[d][k]
    float* Vs  = sm + 2 * 64 * SA2;  // [64][SA2]   V[k][d]
    float* Ps  = sm + 3 * 64 * SA2;  // [64][SA2]   P[q][k]
    float* mk  = sm + 4 * 64 * SA2;  // [64]

    int bh = blockIdx.y;
    int b = bh >> 4;
    int qt = blockIdx.x;
    int t = threadIdx.x, ty = t >> 4, tx = t & 15;

    const float* Qg  = g_Q  + ((size_t)bh * CT + qt * 64) * CDK;
    const float* Ktg = g_Kt + (size_t)bh * CDK * CT;
    const float* Vg  = g_V  + (size_t)bh * CT * CDK;
    const float* mg  = g_maskf + b * CT;

#pragma unroll
    for (int j = 0; j < 4; j++) {
        int idx = j * 256 + t;
        int r = idx >> 4, c4 = (idx & 15) * 4;
        *reinterpret_cast<float4*>(Qs + r * SA2 + c4) =
            *reinterpret_cast<const float4*>(Qg + r * CDK + c4);
    }

    float o[4][4];
#pragma unroll
    for (int i = 0; i < 4; i++)
#pragma unroll
        for (int j = 0; j < 4; j++) o[i][j] = 0.f;
    float qsum[4] = {0.f, 0.f, 0.f, 0.f};

    for (int tile = 0; tile < 32; tile++) {
        __syncthreads();   // prev phase2 done; Q ready on first iter
#pragma unroll
        for (int j = 0; j < 4; j++) {
            int idx = j * 256 + t;
            int r = idx >> 4, c4 = (idx & 15) * 4;
            *reinterpret_cast<float4*>(Kts + r * SA2 + c4) =
                *reinterpret_cast<const float4*>(Ktg + (size_t)r * CT + tile * 64 + c4);
            *reinterpret_cast<float4*>(Vs + r * SA2 + c4) =
                *reinterpret_cast<const float4*>(Vg + (size_t)(tile * 64 + r) * CDK + c4);
        }
        if (t < 64) mk[t] = mg[tile * 64 + t];
        __syncthreads();

        // phase 1: S[q][k] = sum_d Q[q][d] * Kt[d][k]
        float s4[4][4];
#pragma unroll
        for (int i = 0; i < 4; i++)
#pragma unroll
            for (int j = 0; j < 4; j++) s4[i][j] = 0.f;
#pragma unroll 8
        for (int d = 0; d < 64; d += 4) {
            float4 qf[4], kf[4];
#pragma unroll
            for (int i = 0; i < 4; i++) qf[i] = *reinterpret_cast<float4*>(Qs + (ty * 4 + i) * SA2 + d);
#pragma unroll
            for (int c = 0; c < 4; c++) kf[c] = *reinterpret_cast<float4*>(Kts + (d + c) * SA2 + tx * 4);
#pragma unroll
            for (int i = 0; i < 4; i++) {
                s4[i][0] += qf[i].x * kf[0].x + qf[i].y * kf[1].x + qf[i].z * kf[2].x + qf[i].w * kf[3].x;
                s4[i][1] += qf[i].x * kf[0].y + qf[i].y * kf[1].y + qf[i].z * kf[2].y + qf[i].w * kf[3].y;
                s4[i][2] += qf[i].x * kf[0].z + qf[i].y * kf[1].z + qf[i].z * kf[2].z + qf[i].w * kf[3].z;
                s4[i][3] += qf[i].x * kf[0].w + qf[i].y * kf[1].w + qf[i].z * kf[2].w + qf[i].w * kf[3].w;
            }
        }

        // exp / mask / store P / partial row sums
        float m4[4];
#pragma unroll
        for (int j = 0; j < 4; j++) m4[j] = mk[tx * 4 + j];
        float ps[4] = {0.f, 0.f, 0.f, 0.f};
#pragma unroll
        for (int i = 0; i < 4; i++) {
            float4 pr;
            float sv, p;
            sv = fminf(fmaxf(s4[i][0] * ASCALE, -10.f), 10.f);
            p = (m4[0] != 0.f) ? 0.f : __expf(sv); pr.x = p; ps[i] += p;
            sv = fminf(fmaxf(s4[i][1] * ASCALE, -10.f), 10.f);
            p = (m4[1] != 0.f) ? 0.f : __expf(sv); pr.y = p; ps[i] += p;
            sv = fminf(fmaxf(s4[i][2] * ASCALE, -10.f), 10.f);
            p = (m4[2] != 0.f) ? 0.f : __expf(sv); pr.z = p; ps[i] += p;
            sv = fminf(fmaxf(s4[i][3] * ASCALE, -10.f), 10.f);
            p = (m4[3] != 0.f) ? 0.f : __expf(sv); pr.w = p; ps[i] += p;
            *reinterpret_cast<float4*>(Ps + (ty * 4 + i) * SA2 + tx * 4) = pr;
        }
#pragma unroll
        for (int m = 1; m < 16; m <<= 1) {
#pragma unroll
            for (int i = 0; i < 4; i++) ps[i] += __shfl_xor_sync(0xffffffffu, ps[i], m);
        }
#pragma unroll
        for (int i = 0; i < 4; i++) qsum[i] += ps[i];
        __syncthreads();

        // phase 2: O[q][d] += sum_k P[q][k] * V[k][d]
#pragma unroll 8
        for (int k = 0; k < 64; k += 4) {
            float4 pf[4], vf[4];
#pragma unroll
            for (int i = 0; i < 4; i++) pf[i] = *reinterpret_cast<float4*>(Ps + (ty * 4 + i) * SA2 + k);
#pragma unroll
            for (int c = 0; c < 4; c++) vf[c] = *reinterpret_cast<float4*>(Vs + (k + c) * SA2 + tx * 4);
#pragma unroll
            for (int i = 0; i < 4; i++) {
                o[i][0] += pf[i].x * vf[0].x + pf[i].y * vf[1].x + pf[i].z * vf[2].x + pf[i].w * vf[3].x;
                o[i][1] += pf[i].x * vf[0].y + pf[i].y * vf[1].y + pf[i].z * vf[2].y + pf[i].w * vf[3].y;
                o[i][2] += pf[i].x * vf[0].z + pf[i].y * vf[1].z + pf[i].z * vf[2].z + pf[i].w * vf[3].z;
                o[i][3] += pf[i].x * vf[0].w + pf[i].y * vf[1].w + pf[i].z * vf[2].w + pf[i].w * vf[3].w;
            }
        }
    }

    // epilogue: normalize and scatter to [b*T+t][D]
    int h = bh & 15;
#pragma unroll
    for (int i = 0; i < 4; i++) {
        float inv = 1.0f / qsum[i];
        float4 ov;
        ov.x = o[i][0] * inv;
        ov.y = o[i][1] * inv;
        ov.z = o[i][2] * inv;
        ov.w = o[i][3] * inv;
        int q = qt * 64 + ty * 4 + i;
        *reinterpret_cast<float4*>(g_AO + ((size_t)(b * CT + q)) * CD + h * CDK + tx * 4) = ov;
    }
}

// ---------------- launch ----------------
extern "C" void kernel_launch(void* const* d_in, const int* in_sizes, int n_in,
                              void* d_out, int out_size) {
    (void)in_sizes; (void)n_in; (void)out_size;
    const float* x  = (const float*)d_in[0];
    const unsigned char* mraw = (const unsigned char*)d_in[1];
    const float* wq = (const float*)d_in[2];
    const float* bq = (const float*)d_in[3];
    const float* wk = (const float*)d_in[4];
    const float* bk = (const float*)d_in[5];
    const float* wv = (const float*)d_in[6];
    const float* bv = (const float*)d_in[7];
    const float* wo = (const float*)d_in[8];
    const float* bo = (const float*)d_in[9];
    const float* lg = (const float*)d_in[10];
    const float* lb = (const float*)d_in[11];
    float* out = (float*)d_out;

    const int attn_smem = (4 * 64 * SA2 + 64) * 4;   // 69888 bytes
    cudaFuncSetAttribute(attn_kernel, cudaFuncAttributeMaxDynamicSharedMemorySize, attn_smem);

    decode_mask_kernel<<<1, 256>>>(mraw);
    layernorm_kernel<<<NTOK, 256>>>(x, lg, lb);
    gemm_qkv_kernel<<<dim3(CD / GBN, NTOK / GBM, 3), 256>>>(wq, wk, wv, bq, bk, bv);
    l2norm_q_kernel<<<(NBH * CT) / 8, 256>>>();
    l2norm_kt_kernel<<<dim3(CT / 256, NBH), 256>>>();
    attn_kernel<<<dim3(CT / 64, NBH), 256, attn_smem>>>();
    gemm_oproj_kernel<<<dim3(CD / GBN, NTOK / GBM), 256>>>(wo, bo, out);
}

// round 3
// speedup vs baseline: 1.3437x; 1.3437x over previous
#include <cuda_runtime.h>
#include <cuda_bf16.h>

#define CB 4
#define CT 2048
#define CD 1024
#define CH 16
#define CDK 64
#define NTOK 8192      // CB*CT
#define NBH  64        // CB*CH
#define ASCALE 0.125f

typedef __nv_bfloat16 bf16;
typedef __nv_bfloat162 bf162;

// ---------------- scratch ----------------
__device__ __align__(256) bf16 g_Xh[NTOK * CD];
__device__ __align__(256) bf16 g_Xl[NTOK * CD];
__device__ __align__(256) bf16 g_Wh[4 * CD * CD];   // wq,wk,wv,wo
__device__ __align__(256) bf16 g_Wl[4 * CD * CD];
__device__ float g_Q[NTOK * CD];     // [bh][t][dk]
__device__ float g_Kt[NTOK * CD];    // [bh][dk][t]
__device__ float g_V[NTOK * CD];     // [bh][t][dk]
__device__ __align__(256) bf16 g_AOh[NTOK * CD];
__device__ __align__(256) bf16 g_AOl[NTOK * CD];
__device__ float g_maskf[NTOK];

// ---------------- PTX helpers (plain sm_103-safe: mma.sync / ldmatrix / cp.async) ----
__device__ __forceinline__ unsigned smem_u32(const void* p) {
    unsigned a;
    asm("{ .reg .u64 t; cvta.to.shared.u64 t, %1; cvt.u32.u64 %0, t; }" : "=r"(a) : "l"(p));
    return a;
}

#define CP_ASYNC16(d, s) \
    asm volatile("cp.async.cg.shared.global [%0], [%1], 16;" :: "r"(d), "l"(s))
#define CP_COMMIT() asm volatile("cp.async.commit_group;" ::: "memory")
#define CP_WAIT1()  asm volatile("cp.async.wait_group 1;" ::: "memory")
#define CP_WAIT0()  asm volatile("cp.async.wait_group 0;" ::: "memory")

#define LDSM4(r0, r1, r2, r3, a) \
    asm volatile("ldmatrix.sync.aligned.m8n8.x4.shared.b16 {%0,%1,%2,%3}, [%4];" \
        : "=r"(r0), "=r"(r1), "=r"(r2), "=r"(r3) : "r"(a))

#define MMA16816(c, a, b0, b1) \
    asm volatile("mma.sync.aligned.m16n8k16.row.col.f32.bf16.bf16.f32 " \
        "{%0,%1,%2,%3}, {%4,%5,%6,%7}, {%8,%9}, {%0,%1,%2,%3};" \
        : "+f"((c)[0]), "+f"((c)[1]), "+f"((c)[2]), "+f"((c)[3]) \
        : "r"((a)[0]), "r"((a)[1]), "r"((a)[2]), "r"((a)[3]), "r"(b0), "r"(b1))

// ---------------- mask decode ----------------
__global__ void decode_mask_kernel(const unsigned char* __restrict__ raw) {
    __shared__ int s_big, s_nzoff, s_nz4, s_nz23;
    if (threadIdx.x == 0) { s_big = 0; s_nzoff = 0; s_nz4 = 0; s_nz23 = 0; }
    __syncthreads();
    int big = 0, nzoff = 0, nz4 = 0, nz23 = 0;
    for (int i = threadIdx.x; i < NTOK; i += blockDim.x) {
        unsigned char v = raw[i];
        if (v > 1) big = 1;
        if (v != 0) {
            if ((i & 3) != 0) nzoff = 1;
            int m8 = i & 7;
            if (m8 >= 4) nz4 = 1;
            if (m8 == 2 || m8 == 3) nz23 = 1;
        }
    }
    if (big)   atomicOr(&s_big, 1);
    if (nzoff) atomicOr(&s_nzoff, 1);
    if (nz4)   atomicOr(&s_nz4, 1);
    if (nz23)  atomicOr(&s_nz23, 1);
    __syncthreads();
    int cls;
    if (s_big)        cls = s_nz23 ? 2 : 4;
    else if (s_nzoff) cls = 0;
    else              cls = s_nz4 ? 1 : 3;
    for (int i = threadIdx.x; i < NTOK; i += blockDim.x) {
        float m;
        if (cls == 0)      m = raw[i] ? 1.0f : 0.0f;
        else if (cls == 1) m = (((const int*)raw)[i] != 0) ? 1.0f : 0.0f;
        else if (cls == 2) m = (((const float*)raw)[i] != 0.0f) ? 1.0f : 0.0f;
        else if (cls == 3) m = (((const long long*)raw)[i] != 0) ? 1.0f : 0.0f;
        else               m = (((const double*)raw)[i] != 0.0) ? 1.0f : 0.0f;
        g_maskf[i] = m;
    }
}

// ---------------- hi/lo split helpers ----------------
__device__ __forceinline__ void split_store4(bf16* hp, bf16* lp, float a, float b, float c, float d) {
    bf16 ha = __float2bfloat16_rn(a), hb = __float2bfloat16_rn(b);
    bf16 hc = __float2bfloat16_rn(c), hd = __float2bfloat16_rn(d);
    bf16 la = __float2bfloat16_rn(a - __bfloat162float(ha));
    bf16 lb = __float2bfloat16_rn(b - __bfloat162float(hb));
    bf16 lc = __float2bfloat16_rn(c - __bfloat162float(hc));
    bf16 ld = __float2bfloat16_rn(d - __bfloat162float(hd));
    reinterpret_cast<bf162*>(hp)[0] = __halves2bfloat162(ha, hb);
    reinterpret_cast<bf162*>(hp)[1] = __halves2bfloat162(hc, hd);
    reinterpret_cast<bf162*>(lp)[0] = __halves2bfloat162(la, lb);
    reinterpret_cast<bf162*>(lp)[1] = __halves2bfloat162(lc, ld);
}

// ---------------- layernorm -> bf16 hi/lo ----------------
__global__ void layernorm_kernel(const float* __restrict__ x,
                                 const float* __restrict__ gam,
                                 const float* __restrict__ bet) {
    int row = blockIdx.x;
    int t = threadIdx.x;
    const float4* xr = reinterpret_cast<const float4*>(x + (size_t)row * CD);
    float4 v = xr[t];
    float s = v.x + v.y + v.z + v.w;
    float q = v.x * v.x + v.y * v.y + v.z * v.z + v.w * v.w;
    __shared__ float red[20];
#pragma unroll
    for (int m = 16; m > 0; m >>= 1) {
        s += __shfl_xor_sync(0xffffffffu, s, m);
        q += __shfl_xor_sync(0xffffffffu, q, m);
    }
    int w = t >> 5, lane = t & 31;
    if (lane == 0) { red[w] = s; red[8 + w] = q; }
    __syncthreads();
    if (t == 0) {
        float S = 0.f, Qq = 0.f;
#pragma unroll
        for (int i = 0; i < 8; i++) { S += red[i]; Qq += red[8 + i]; }
        float mu = S * (1.0f / CD);
        float var = Qq * (1.0f / CD) - mu * mu;
        red[16] = mu;
        red[17] = rsqrtf(var + 1e-5f);
    }
    __syncthreads();
    float mu = red[16], inv = red[17];
    float4 g4 = reinterpret_cast<const float4*>(gam)[t];
    float4 b4 = reinterpret_cast<const float4*>(bet)[t];
    float ox = (v.x - mu) * inv * g4.x + b4.x;
    float oy = (v.y - mu) * inv * g4.y + b4.y;
    float oz = (v.z - mu) * inv * g4.z + b4.z;
    float ow = (v.w - mu) * inv * g4.w + b4.w;
    size_t base = (size_t)row * CD + t * 4;
    split_store4(g_Xh + base, g_Xl + base, ox, oy, oz, ow);
}

// ---------------- weight fp32 -> bf16 hi/lo ----------------
__global__ void convert_w_kernel(const float* __restrict__ wq, const float* __restrict__ wk,
                                 const float* __restrict__ wv, const float* __restrict__ wo) {
    int wsel = blockIdx.y;
    const float* src = (wsel == 0) ? wq : (wsel == 1) ? wk : (wsel == 2) ? wv : wo;
    size_t base = (size_t)wsel * CD * CD;
    size_t i4 = ((size_t)blockIdx.x * blockDim.x + threadIdx.x) * 4;
    float4 v = *reinterpret_cast<const float4*>(src + i4);
    split_store4(g_Wh + base + i4, g_Wl + base + i4, v.x, v.y, v.z, v.w);
}

// ---------------- HMMA GEMM core ----------------
// C[128x128] = (Ah+Al)[128x1024] * (Wh+Wl)[128x1024]^T  (3-pass hi/lo split)
// smem: 2 stages x 4 buffers (Ah,Al,Wh,Wl), each 128 rows x 32 bf16, row stride 80B.
#define RS 80                       // smem row stride (bytes) = 40 bf16
#define BUF (128 * RS)              // 10240 B per buffer
#define STAGE (4 * BUF)             // 40960 B per stage
#define GEMM_SMEM (2 * STAGE)       // 81920 B

__device__ __forceinline__ void gemm_load_stage(unsigned sb, int stage, int c,
                                                const bf16* Ah, const bf16* Al,
                                                const bf16* Wh, const bf16* Wl) {
    int t = threadIdx.x;
    const char* srcs[4] = { (const char*)Ah, (const char*)Al,
                            (const char*)Wh, (const char*)Wl };
    unsigned dbase = sb + stage * STAGE;
#pragma unroll
    for (int q = 0; q < 4; q++) {
        const char* sp = srcs[q];
#pragma unroll
        for (int u = 0; u < 2; u++) {
            int i = u * 256 + t;          // 0..511
            int row = i >> 2, seg = i & 3;
            const char* g = sp + (size_t)row * 2048 + (size_t)c * 64 + seg * 16;
            unsigned d = dbase + q * BUF + row * RS + seg * 16;
            CP_ASYNC16(d, g);
        }
    }
    CP_COMMIT();
}

__device__ __forceinline__ void gemm_core_mma(unsigned sb,
                                              const bf16* Ah, const bf16* Al,
                                              const bf16* Wh, const bf16* Wl,
                                              float acc[4][4][4]) {
    int t = threadIdx.x;
    int warp = t >> 5, lane = t & 31;
    int wm = warp >> 2, wn = warp & 3;       // 2 x 4 warp grid
    int quad = lane >> 3, r = lane & 7;

    gemm_load_stage(sb, 0, 0, Ah, Al, Wh, Wl);

    for (int c = 0; c < 32; c++) {
        int cur = c & 1;
        if (c + 1 < 32) {
            gemm_load_stage(sb, cur ^ 1, c + 1, Ah, Al, Wh, Wl);
            CP_WAIT1();
        } else {
            CP_WAIT0();
        }
        __syncthreads();

        unsigned abh = sb + cur * STAGE;             // Ah buffer
        unsigned abl = abh + BUF;                    // Al
        unsigned wbh = abh + 2 * BUF;                // Wh
        unsigned wbl = abh + 3 * BUF;                // Wl

#pragma unroll
        for (int k0 = 0; k0 < 32; k0 += 16) {
            unsigned ah[4][4], al[4][4], bh[2][4], bl[2][4];
            int acolb = (k0 + (quad >> 1) * 8) * 2;
            int arow_off = (quad & 1) * 8 + r;
#pragma unroll
            for (int mi = 0; mi < 4; mi++) {
                unsigned addr = (wm * 64 + mi * 16 + arow_off) * RS + acolb;
                LDSM4(ah[mi][0], ah[mi][1], ah[mi][2], ah[mi][3], abh + addr);
                LDSM4(al[mi][0], al[mi][1], al[mi][2], al[mi][3], abl + addr);
            }
            int bcolb = (k0 + (quad & 1) * 8) * 2;
            int brow_off = (quad >> 1) * 8 + r;
#pragma unroll
            for (int bj = 0; bj < 2; bj++) {
                unsigned addr = (wn * 32 + bj * 16 + brow_off) * RS + bcolb;
                LDSM4(bh[bj][0], bh[bj][1], bh[bj][2], bh[bj][3], wbh + addr);
                LDSM4(bl[bj][0], bl[bj][1], bl[bj][2], bl[bj][3], wbl + addr);
            }
#pragma unroll
            for (int mi = 0; mi < 4; mi++) {
#pragma unroll
                for (int nt = 0; nt < 4; nt++) {
                    int bj = nt >> 1, sel = (nt & 1) * 2;
                    MMA16816(acc[mi][nt], ah[mi], bh[bj][sel], bh[bj][sel + 1]);
                    MMA16816(acc[mi][nt], al[mi], bh[bj][sel], bh[bj][sel + 1]);
                    MMA16816(acc[mi][nt], ah[mi], bl[bj][sel], bl[bj][sel + 1]);
                }
            }
        }
        __syncthreads();
    }
}

// write accumulators into smem C[128][132] (float), then sync
__device__ __forceinline__ void gemm_stage_c(float* Cs, float acc[4][4][4]) {
    int t = threadIdx.x;
    int warp = t >> 5, lane = t & 31;
    int wm = warp >> 2, wn = warp & 3;
#pragma unroll
    for (int mi = 0; mi < 4; mi++) {
#pragma unroll
        for (int nt = 0; nt < 4; nt++) {
            int row = wm * 64 + mi * 16 + (lane >> 2);
            int col = wn * 32 + nt * 8 + (lane & 3) * 2;
            Cs[row * 132 + col]       = acc[mi][nt][0];
            Cs[row * 132 + col + 1]   = acc[mi][nt][1];
            Cs[(row + 8) * 132 + col]     = acc[mi][nt][2];
            Cs[(row + 8) * 132 + col + 1] = acc[mi][nt][3];
        }
    }
    __syncthreads();
}

// ---------------- QKV projection ----------------
__global__ __launch_bounds__(256, 1) void gemm_qkv_mma(
    const float* __restrict__ bq, const float* __restrict__ bk, const float* __restrict__ bv) {
    extern __shared__ char smem[];
    unsigned sb = smem_u32(smem);
    int z = blockIdx.z;
    const bf16* Wh = g_Wh + (size_t)z * CD * CD + (size_t)blockIdx.x * 128 * CD;
    const bf16* Wl = g_Wl + (size_t)z * CD * CD + (size_t)blockIdx.x * 128 * CD;
    const bf16* Ah = g_Xh + (size_t)blockIdx.y * 128 * CD;
    const bf16* Al = g_Xl + (size_t)blockIdx.y * 128 * CD;
    const float* bias = (z == 0) ? bq : (z == 1) ? bk : bv;

    float acc[4][4][4];
#pragma unroll
    for (int i = 0; i < 4; i++)
#pragma unroll
        for (int j = 0; j < 4; j++)
#pragma unroll
            for (int k = 0; k < 4; k++) acc[i][j][k] = 0.f;

    gemm_core_mma(sb, Ah, Al, Wh, Wl, acc);
    float* Cs = reinterpret_cast<float*>(smem);
    gemm_stage_c(Cs, acc);

    int t = threadIdx.x;
    int row = t >> 1, half = t & 1;
    int n = blockIdx.y * 128 + row;
    int bb = n >> 11, tok = n & 2047;
    int e0 = blockIdx.x * 128 + half * 64;
    int h = e0 >> 6;
    int bh = bb * CH + h;
    const float* cr = Cs + row * 132 + half * 64;

    if (z == 1) {
        float* dst = g_Kt + (size_t)bh * CDK * CT + tok;
#pragma unroll
        for (int j = 0; j < 64; j++)
            dst[(size_t)j * CT] = cr[j] + __ldg(bias + e0 + j);
    } else {
        float* dst = ((z == 0) ? g_Q : g_V) + ((size_t)bh * CT + tok) * CDK;
#pragma unroll
        for (int j0 = 0; j0 < 64; j0 += 4) {
            float4 o;
            o.x = cr[j0 + 0] + __ldg(bias + e0 + j0 + 0);
            o.y = cr[j0 + 1] + __ldg(bias + e0 + j0 + 1);
            o.z = cr[j0 + 2] + __ldg(bias + e0 + j0 + 2);
            o.w = cr[j0 + 3] + __ldg(bias + e0 + j0 + 3);
            *reinterpret_cast<float4*>(dst + j0) = o;
        }
    }
}

// ---------------- output projection (*0.5) ----------------
__global__ __launch_bounds__(256, 1) void gemm_o_mma(const float* __restrict__ bo,
                                                     float* __restrict__ out) {
    extern __shared__ char smem[];
    unsigned sb = smem_u32(smem);
    const bf16* Wh = g_Wh + (size_t)3 * CD * CD + (size_t)blockIdx.x * 128 * CD;
    const bf16* Wl = g_Wl + (size_t)3 * CD * CD + (size_t)blockIdx.x * 128 * CD;
    const bf16* Ah = g_AOh + (size_t)blockIdx.y * 128 * CD;
    const bf16* Al = g_AOl + (size_t)blockIdx.y * 128 * CD;

    float acc[4][4][4];
#pragma unroll
    for (int i = 0; i < 4; i++)
#pragma unroll
        for (int j = 0; j < 4; j++)
#pragma unroll
            for (int k = 0; k < 4; k++) acc[i][j][k] = 0.f;

    gemm_core_mma(sb, Ah, Al, Wh, Wl, acc);
    float* Cs = reinterpret_cast<float*>(smem);
    gemm_stage_c(Cs, acc);

    int t = threadIdx.x;
    int row = t >> 1, half = t & 1;
    int n = blockIdx.y * 128 + row;
    int e0 = blockIdx.x * 128 + half * 64;
    const float* cr = Cs + row * 132 + half * 64;
    float* dst = out + (size_t)n * CD + e0;
#pragma unroll
    for (int j0 = 0; j0 < 64; j0 += 4) {
        float4 o;
        o.x = (cr[j0 + 0] + __ldg(bo + e0 + j0 + 0)) * 0.5f;
        o.y = (cr[j0 + 1] + __ldg(bo + e0 + j0 + 1)) * 0.5f;
        o.z = (cr[j0 + 2] + __ldg(bo + e0 + j0 + 2)) * 0.5f;
        o.w = (cr[j0 + 3] + __ldg(bo + e0 + j0 + 3)) * 0.5f;
        *reinterpret_cast<float4*>(dst + j0) = o;
    }
}

// ---------------- L2 norms ----------------
__global__ void l2norm_q_kernel() {
    int gid = blockIdx.x * blockDim.x + threadIdx.x;
    int w = gid >> 5, lane = gid & 31;
    float2* p = reinterpret_cast<float2*>(g_Q + (size_t)w * CDK) + lane;
    float2 v = *p;
    float s = v.x * v.x + v.y * v.y;
#pragma unroll
    for (int m = 16; m > 0; m >>= 1) s += __shfl_xor_sync(0xffffffffu, s, m);
    float inv = 1.0f / fmaxf(sqrtf(s), 1e-8f);
    v.x *= inv; v.y *= inv;
    *p = v;
}

__global__ void l2norm_kt_kernel() {
    int bh = blockIdx.y;
    int tok = blockIdx.x * 256 + threadIdx.x;
    float* base = g_Kt + (size_t)bh * CDK * CT + tok;
    float v[CDK];
    float s = 0.f;
#pragma unroll
    for (int d = 0; d < CDK; d++) { v[d] = base[(size_t)d * CT]; s += v[d] * v[d]; }
    float inv = 1.0f / fmaxf(sqrtf(s), 1e-8f);
#pragma unroll
    for (int d = 0; d < CDK; d++) base[(size_t)d * CT] = v[d] * inv;
}

// ---------------- attention (fp32) ----------------
#define SA2 68

__global__ __launch_bounds__(256) void attn_kernel() {
    extern __shared__ float sm[];
    float* Qs  = sm;
    float* Kts = sm + 64 * SA2;
    float* Vs  = sm + 2 * 64 * SA2;
    float* Ps  = sm + 3 * 64 * SA2;
    float* mk  = sm + 4 * 64 * SA2;

    int bh = blockIdx.y;
    int b = bh >> 4;
    int qt = blockIdx.x;
    int t = threadIdx.x, ty = t >> 4, tx = t & 15;

    const float* Qg  = g_Q  + ((size_t)bh * CT + qt * 64) * CDK;
    const float* Ktg = g_Kt + (size_t)bh * CDK * CT;
    const float* Vg  = g_V  + (size_t)bh * CT * CDK;
    const float* mg  = g_maskf + b * CT;

#pragma unroll
    for (int j = 0; j < 4; j++) {
        int idx = j * 256 + t;
        int r = idx >> 4, c4 = (idx & 15) * 4;
        *reinterpret_cast<float4*>(Qs + r * SA2 + c4) =
            *reinterpret_cast<const float4*>(Qg + r * CDK + c4);
    }

    float o[4][4];
#pragma unroll
    for (int i = 0; i < 4; i++)
#pragma unroll
        for (int j = 0; j < 4; j++) o[i][j] = 0.f;
    float qsum[4] = {0.f, 0.f, 0.f, 0.f};

    for (int tile = 0; tile < 32; tile++) {
        __syncthreads();
#pragma unroll
        for (int j = 0; j < 4; j++) {
            int idx = j * 256 + t;
            int r = idx >> 4, c4 = (idx & 15) * 4;
            *reinterpret_cast<float4*>(Kts + r * SA2 + c4) =
                *reinterpret_cast<const float4*>(Ktg + (size_t)r * CT + tile * 64 + c4);
            *reinterpret_cast<float4*>(Vs + r * SA2 + c4) =
                *reinterpret_cast<const float4*>(Vg + (size_t)(tile * 64 + r) * CDK + c4);
        }
        if (t < 64) mk[t] = mg[tile * 64 + t];
        __syncthreads();

        float s4[4][4];
#pragma unroll
        for (int i = 0; i < 4; i++)
#pragma unroll
            for (int j = 0; j < 4; j++) s4[i][j] = 0.f;
#pragma unroll 8
        for (int d = 0; d < 64; d += 4) {
            float4 qf[4], kf[4];
#pragma unroll
            for (int i = 0; i < 4; i++) qf[i] = *reinterpret_cast<float4*>(Qs + (ty * 4 + i) * SA2 + d);
#pragma unroll
            for (int c = 0; c < 4; c++) kf[c] = *reinterpret_cast<float4*>(Kts + (d + c) * SA2 + tx * 4);
#pragma unroll
            for (int i = 0; i < 4; i++) {
                s4[i][0] += qf[i].x * kf[0].x + qf[i].y * kf[1].x + qf[i].z * kf[2].x + qf[i].w * kf[3].x;
                s4[i][1] += qf[i].x * kf[0].y + qf[i].y * kf[1].y + qf[i].z * kf[2].y + qf[i].w * kf[3].y;
                s4[i][2] += qf[i].x * kf[0].z + qf[i].y * kf[1].z + qf[i].z * kf[2].z + qf[i].w * kf[3].z;
                s4[i][3] += qf[i].x * kf[0].w + qf[i].y * kf[1].w + qf[i].z * kf[2].w + qf[i].w * kf[3].w;
            }
        }

        float m4[4];
#pragma unroll
        for (int j = 0; j < 4; j++) m4[j] = mk[tx * 4 + j];
        float ps[4] = {0.f, 0.f, 0.f, 0.f};
#pragma unroll
        for (int i = 0; i < 4; i++) {
            float4 pr;
            float sv, p;
            sv = fminf(fmaxf(s4[i][0] * ASCALE, -10.f), 10.f);
            p = (m4[0] != 0.f) ? 0.f : __expf(sv); pr.x = p; ps[i] += p;
            sv = fminf(fmaxf(s4[i][1] * ASCALE, -10.f), 10.f);
            p = (m4[1] != 0.f) ? 0.f : __expf(sv); pr.y = p; ps[i] += p;
            sv = fminf(fmaxf(s4[i][2] * ASCALE, -10.f), 10.f);
            p = (m4[2] != 0.f) ? 0.f : __expf(sv); pr.z = p; ps[i] += p;
            sv = fminf(fmaxf(s4[i][3] * ASCALE, -10.f), 10.f);
            p = (m4[3] != 0.f) ? 0.f : __expf(sv); pr.w = p; ps[i] += p;
            *reinterpret_cast<float4*>(Ps + (ty * 4 + i) * SA2 + tx * 4) = pr;
        }
#pragma unroll
        for (int m = 1; m < 16; m <<= 1) {
#pragma unroll
            for (int i = 0; i < 4; i++) ps[i] += __shfl_xor_sync(0xffffffffu, ps[i], m);
        }
#pragma unroll
        for (int i = 0; i < 4; i++) qsum[i] += ps[i];
        __syncthreads();

#pragma unroll 8
        for (int k = 0; k < 64; k += 4) {
            float4 pf[4], vf[4];
#pragma unroll
            for (int i = 0; i < 4; i++) pf[i] = *reinterpret_cast<float4*>(Ps + (ty * 4 + i) * SA2 + k);
#pragma unroll
            for (int c = 0; c < 4; c++) vf[c] = *reinterpret_cast<float4*>(Vs + (k + c) * SA2 + tx * 4);
#pragma unroll
            for (int i = 0; i < 4; i++) {
                o[i][0] += pf[i].x * vf[0].x + pf[i].y * vf[1].x + pf[i].z * vf[2].x + pf[i].w * vf[3].x;
                o[i][1] += pf[i].x * vf[0].y + pf[i].y * vf[1].y + pf[i].z * vf[2].y + pf[i].w * vf[3].y;
                o[i][2] += pf[i].x * vf[0].z + pf[i].y * vf[1].z + pf[i].z * vf[2].z + pf[i].w * vf[3].z;
                o[i][3] += pf[i].x * vf[0].w + pf[i].y * vf[1].w + pf[i].z * vf[2].w + pf[i].w * vf[3].w;
            }
        }
    }

    int h = bh & 15;
#pragma unroll
    for (int i = 0; i < 4; i++) {
        float inv = 1.0f / qsum[i];
        int q = qt * 64 + ty * 4 + i;
        size_t base = ((size_t)(b * CT + q)) * CD + h * CDK + tx * 4;
        split_store4(g_AOh + base, g_AOl + base,
                     o[i][0] * inv, o[i][1] * inv, o[i][2] * inv, o[i][3] * inv);
    }
}

// ---------------- launch ----------------
extern "C" void kernel_launch(void* const* d_in, const int* in_sizes, int n_in,
                              void* d_out, int out_size) {
    (void)in_sizes; (void)n_in; (void)out_size;
    const float* x  = (const float*)d_in[0];
    const unsigned char* mraw = (const unsigned char*)d_in[1];
    const float* wq = (const float*)d_in[2];
    const float* bq = (const float*)d_in[3];
    const float* wk = (const float*)d_in[4];
    const float* bk = (const float*)d_in[5];
    const float* wv = (const float*)d_in[6];
    const float* bv = (const float*)d_in[7];
    const float* wo = (const float*)d_in[8];
    const float* bo = (const float*)d_in[9];
    const float* lg = (const float*)d_in[10];
    const float* lb = (const float*)d_in[11];
    float* out = (float*)d_out;

    const int attn_smem = (4 * 64 * SA2 + 64) * 4;
    cudaFuncSetAttribute(attn_kernel, cudaFuncAttributeMaxDynamicSharedMemorySize, attn_smem);
    cudaFuncSetAttribute(gemm_qkv_mma, cudaFuncAttributeMaxDynamicSharedMemorySize, GEMM_SMEM);
    cudaFuncSetAttribute(gemm_o_mma, cudaFuncAttributeMaxDynamicSharedMemorySize, GEMM_SMEM);

    decode_mask_kernel<<<1, 256>>>(mraw);
    layernorm_kernel<<<NTOK, 256>>>(x, lg, lb);
    convert_w_kernel<<<dim3(1024, 4), 256>>>(wq, wk, wv, wo);
    gemm_qkv_mma<<<dim3(CD / 128, NTOK / 128, 3), 256, GEMM_SMEM>>>(bq, bk, bv);
    l2norm_q_kernel<<<(NBH * CT) / 8, 256>>>();
    l2norm_kt_kernel<<<dim3(CT / 256, NBH), 256>>>();
    attn_kernel<<<dim3(CT / 64, NBH), 256, attn_smem>>>();
    gemm_o_mma<<<dim3(CD / 128, NTOK / 128), 256, GEMM_SMEM>>>(bo, out);
}